// round 3
// baseline (speedup 1.0000x reference)
#include <cuda_runtime.h>
#include <cstdint>

#define N_ENT 50000
#define R_REL 16
#define D_EMB 64
#define F_IN  128
#define E_EDGE 100000
#define NEDGE (R_REL * E_EDGE)          // 1.6M
#define NK (N_ENT * R_REL)              // 800000 segments (row, rel)
#define KTOT (R_REL * D_EMB)            // 1024
#define NL 2

// ---------------- scratch (device globals; allocation-free rule) ------------
__device__ float g_emb[(size_t)N_ENT * D_EMB];                 // 12.8 MB
__device__ float g_stack[(size_t)N_ENT * KTOT];                // 204.8 MB
__device__ float g_Wcat[NL * KTOT * D_EMB];                    // 512 KB
__device__ int   g_counts[NK];
__device__ int   g_rowstart[NK + 1];
__device__ int   g_cursor[NK];
__device__ int2  g_recs[NEDGE];                                // {col, val bits}

#define SCHUNK 1024
#define NCH ((NK + SCHUNK - 1) / SCHUNK)                       // 782
__device__ int   g_part[NCH];

// ---------------------------------------------------------------------------
// Input GEMM: g_emb[n,d] = sum_k x[n,k] * ent_emb[k,d]   (K=128)
// ---------------------------------------------------------------------------
#define KS_IN 132

__global__ void k_input_gemm(const float* __restrict__ x,
                             const float* __restrict__ ent_emb,
                             int nrows) {
    extern __shared__ float smem[];
    float* sA  = smem;                 // [64][KS_IN]
    float* sBt = smem + 64 * KS_IN;    // [64][KS_IN]

    const int tid  = threadIdx.x;
    const int base = blockIdx.x * 64;

    for (int idx = tid; idx < F_IN * D_EMB; idx += 256) {
        int k = idx / D_EMB, d = idx % D_EMB;
        sBt[d * KS_IN + k] = ent_emb[idx];
    }
    for (int idx4 = tid; idx4 < 64 * (F_IN / 4); idx4 += 256) {
        int row = idx4 / (F_IN / 4), kq = idx4 % (F_IN / 4);
        float4 v = make_float4(0.f, 0.f, 0.f, 0.f);
        if (base + row < nrows)
            v = reinterpret_cast<const float4*>(x + (size_t)(base + row) * F_IN)[kq];
        *reinterpret_cast<float4*>(&sA[row * KS_IN + kq * 4]) = v;
    }
    __syncthreads();

    const int cs = tid & 15;
    const int rs = tid >> 4;
    float acc[4][4];
#pragma unroll
    for (int i = 0; i < 4; i++)
#pragma unroll
        for (int j = 0; j < 4; j++) acc[i][j] = 0.f;

#pragma unroll 8
    for (int kq = 0; kq < F_IN / 4; kq++) {
        float4 a[4], b[4];
#pragma unroll
        for (int i = 0; i < 4; i++)
            a[i] = *reinterpret_cast<const float4*>(&sA[(rs + 16 * i) * KS_IN + kq * 4]);
#pragma unroll
        for (int j = 0; j < 4; j++)
            b[j] = *reinterpret_cast<const float4*>(&sBt[(cs + 16 * j) * KS_IN + kq * 4]);
#pragma unroll
        for (int i = 0; i < 4; i++)
#pragma unroll
            for (int j = 0; j < 4; j++)
                acc[i][j] += a[i].x * b[j].x + a[i].y * b[j].y +
                             a[i].z * b[j].z + a[i].w * b[j].w;
    }

#pragma unroll
    for (int i = 0; i < 4; i++) {
        int row = base + rs + 16 * i;
        if (row < nrows) {
#pragma unroll
            for (int j = 0; j < 4; j++)
                g_emb[(size_t)row * D_EMB + cs + 16 * j] = acc[i][j];
        }
    }
}

// ---------------------------------------------------------------------------
// CSR build over keys = row*16 + rel
// ---------------------------------------------------------------------------
__global__ void k_zero_counts() {
    int i = blockIdx.x * blockDim.x + threadIdx.x;
    if (i < NK / 4)
        reinterpret_cast<int4*>(g_counts)[i] = make_int4(0, 0, 0, 0);
}

__global__ void k_hist(const int* __restrict__ erow) {
    int i = blockIdx.x * blockDim.x + threadIdx.x;
    if (i >= NEDGE) return;
    int r = i / E_EDGE;
    int key = __ldg(erow + i) * R_REL + r;
    atomicAdd(&g_counts[key], 1);
}

__global__ void k_scan1() {
    __shared__ int ss[256];
    int b = blockIdx.x, t = threadIdx.x;
    int base = b * SCHUNK + t * 4;
    int4 c = make_int4(0, 0, 0, 0);
    if (base < NK) c = *reinterpret_cast<const int4*>(&g_counts[base]);
    int s = c.x + c.y + c.z + c.w;
    ss[t] = s;
    __syncthreads();
    for (int off = 1; off < 256; off <<= 1) {
        int v = (t >= off) ? ss[t - off] : 0;
        __syncthreads();
        ss[t] += v;
        __syncthreads();
    }
    int excl = ss[t] - s;
    if (t == 255) g_part[b] = ss[t];
    if (base < NK) {
        int r = excl;
        g_rowstart[base + 0] = r; r += c.x;
        g_rowstart[base + 1] = r; r += c.y;
        g_rowstart[base + 2] = r; r += c.z;
        g_rowstart[base + 3] = r;
    }
}

__global__ void k_scan2() {
    __shared__ int sp[1024];
    int t = threadIdx.x;
    int v = (t < NCH) ? g_part[t] : 0;
    sp[t] = v;
    __syncthreads();
    for (int off = 1; off < 1024; off <<= 1) {
        int x = (t >= off) ? sp[t - off] : 0;
        __syncthreads();
        sp[t] += x;
        __syncthreads();
    }
    if (t < NCH) g_part[t] = sp[t] - v;          // exclusive chunk offsets
    if (t == 1023) g_rowstart[NK] = sp[1023];    // total
}

__global__ void k_scan3() {
    int i = blockIdx.x * blockDim.x + threadIdx.x;
    if (i < NK) {
        int v = g_rowstart[i] + g_part[i >> 10];
        g_rowstart[i] = v;
        g_cursor[i] = v;
    }
}

__global__ void k_place(const int* __restrict__ erow,
                        const int* __restrict__ ecol,
                        const float* __restrict__ eval) {
    int i = blockIdx.x * blockDim.x + threadIdx.x;
    if (i >= NEDGE) return;
    int r = i / E_EDGE;
    int key = __ldg(erow + i) * R_REL + r;
    int pos = atomicAdd(&g_cursor[key], 1);
    g_recs[pos] = make_int2(__ldg(ecol + i), __float_as_int(__ldg(eval + i)));
}

// ---------------------------------------------------------------------------
// Wcat[l][(r*64+e)*64 + d] = rel_trans[l][r][d][e]
// ---------------------------------------------------------------------------
__global__ void k_wcat(const float* __restrict__ rel_trans) {
    int i = blockIdx.x * blockDim.x + threadIdx.x;
    if (i >= NL * R_REL * D_EMB * D_EMB) return;
    int e = i & 63;
    int d = (i >> 6) & 63;
    int r = (i >> 12) & 15;
    int l = i >> 16;
    g_Wcat[l * (KTOT * D_EMB) + ((r << 6) + e) * D_EMB + d] = rel_trans[i];
}

// ---------------------------------------------------------------------------
// Gather-aggregate: for key=(row,rel): g_stack[key*64 + :] = sum val*emb[col]
// One warp per key; lane covers 2 floats. Atomic-free; emb is L2-hot.
// ---------------------------------------------------------------------------
__global__ void k_gather() {
    int key  = blockIdx.x * 8 + (threadIdx.x >> 5);
    int lane = threadIdx.x & 31;
    int s = __ldg(&g_rowstart[key]);
    int e = __ldg(&g_rowstart[key + 1]);
    float ax = 0.f, ay = 0.f;
    for (int j = s; j < e; j++) {
        int2 rec = __ldg(&g_recs[j]);
        float v = __int_as_float(rec.y);
        float2 p = *reinterpret_cast<const float2*>(
            &g_emb[(size_t)rec.x * D_EMB + lane * 2]);
        ax = fmaf(v, p.x, ax);
        ay = fmaf(v, p.y, ay);
    }
    *reinterpret_cast<float2*>(&g_stack[(size_t)key * D_EMB + lane * 2]) =
        make_float2(ax, ay);
}

// ---------------------------------------------------------------------------
// Big GEMM + ReLU: g_emb[n,d] = relu( sum_k g_stack[n,k] * Wcat[l][k,d] )
// K=1024. Block 128x64, 256 threads, thread tile 4 rows x 8 cols.
// Packed fma.rn.f32x2. All buffers referenced as device globals IN KERNEL
// (passing __device__ symbols as args from host was round-2's fatal bug).
// ---------------------------------------------------------------------------
#define BM 128
#define BK 64
#define SA_S 68
#define SB_S 68

__global__ void __launch_bounds__(256)
k_gemm_relu(int layer, int nrows) {
    extern __shared__ float sm[];
    float* sA = sm;                 // [BM][SA_S]
    float* sB = sm + BM * SA_S;     // [BK][SB_S]

    const float* A = g_stack;
    const float* B = g_Wcat + (size_t)layer * KTOT * D_EMB;
    float* C       = g_emb;

    const int tid  = threadIdx.x;
    const int base = blockIdx.x * BM;
    const int tr = tid >> 3;        // 0..31 -> rows [tr*4, tr*4+4)
    const int tc = tid & 7;         // 0..7  -> cols [tc*8, tc*8+8)

    unsigned long long acc[4][4];
#pragma unroll
    for (int i = 0; i < 4; i++)
#pragma unroll
        for (int j = 0; j < 4; j++) acc[i][j] = 0ull;

    for (int kc = 0; kc < KTOT; kc += BK) {
        // A tile: 128x64 floats (2048 float4, 8/thread), coalesced
#pragma unroll
        for (int i = 0; i < 8; i++) {
            int idx4 = tid + i * 256;
            int row = idx4 >> 4;
            int kq  = idx4 & 15;
            float4 v = make_float4(0.f, 0.f, 0.f, 0.f);
            if (base + row < nrows)
                v = *reinterpret_cast<const float4*>(
                    &A[(size_t)(base + row) * KTOT + kc + kq * 4]);
            *reinterpret_cast<float4*>(&sA[row * SA_S + kq * 4]) = v;
        }
        // B tile: 64x64 floats (1024 float4, 4/thread)
#pragma unroll
        for (int i = 0; i < 4; i++) {
            int idx4 = tid + i * 256;
            int k  = idx4 >> 4;
            int dq = idx4 & 15;
            *reinterpret_cast<float4*>(&sB[k * SB_S + dq * 4]) =
                *reinterpret_cast<const float4*>(&B[(size_t)(kc + k) * D_EMB + dq * 4]);
        }
        __syncthreads();

#pragma unroll
        for (int k4 = 0; k4 < BK; k4 += 4) {
            float4 av[4];
#pragma unroll
            for (int i = 0; i < 4; i++)
                av[i] = *reinterpret_cast<const float4*>(&sA[(tr * 4 + i) * SA_S + k4]);
#pragma unroll
            for (int kk = 0; kk < 4; kk++) {
                int k = k4 + kk;
                ulonglong2 b01 = *reinterpret_cast<const ulonglong2*>(&sB[k * SB_S + tc * 8]);
                ulonglong2 b23 = *reinterpret_cast<const ulonglong2*>(&sB[k * SB_S + tc * 8 + 4]);
                unsigned long long bp0 = b01.x, bp1 = b01.y, bp2 = b23.x, bp3 = b23.y;
#pragma unroll
                for (int i = 0; i < 4; i++) {
                    float a = (kk == 0) ? av[i].x : (kk == 1) ? av[i].y
                             : (kk == 2) ? av[i].z : av[i].w;
                    unsigned long long a2;
                    asm("mov.b64 %0, {%1, %1};" : "=l"(a2) : "f"(a));
                    asm("fma.rn.f32x2 %0, %1, %2, %0;" : "+l"(acc[i][0]) : "l"(a2), "l"(bp0));
                    asm("fma.rn.f32x2 %0, %1, %2, %0;" : "+l"(acc[i][1]) : "l"(a2), "l"(bp1));
                    asm("fma.rn.f32x2 %0, %1, %2, %0;" : "+l"(acc[i][2]) : "l"(a2), "l"(bp2));
                    asm("fma.rn.f32x2 %0, %1, %2, %0;" : "+l"(acc[i][3]) : "l"(a2), "l"(bp3));
                }
            }
        }
        __syncthreads();
    }

#pragma unroll
    for (int i = 0; i < 4; i++) {
        int row = base + tr * 4 + i;
        if (row < nrows) {
#pragma unroll
            for (int j = 0; j < 4; j++) {
                float2 v = *reinterpret_cast<float2*>(&acc[i][j]);
                v.x = fmaxf(v.x, 0.f);
                v.y = fmaxf(v.y, 0.f);
                *reinterpret_cast<float2*>(
                    &C[(size_t)row * D_EMB + tc * 8 + j * 2]) = v;
            }
        }
    }
}

// ---------------------------------------------------------------------------
// L2 normalize rows
// ---------------------------------------------------------------------------
__global__ void k_normalize(float* __restrict__ out) {
    int row  = blockIdx.x * 8 + (threadIdx.x >> 5);
    int lane = threadIdx.x & 31;
    if (row >= N_ENT) return;
    const float* e = g_emb + (size_t)row * D_EMB;
    float v0 = e[lane], v1 = e[lane + 32];
    float ss = v0 * v0 + v1 * v1;
#pragma unroll
    for (int o = 16; o > 0; o >>= 1) ss += __shfl_xor_sync(0xFFFFFFFFu, ss, o);
    float s = 1.0f / fmaxf(sqrtf(ss), 1e-12f);
    out[(size_t)row * D_EMB + lane]      = v0 * s;
    out[(size_t)row * D_EMB + lane + 32] = v1 * s;
}

// ---------------------------------------------------------------------------
extern "C" void kernel_launch(void* const* d_in, const int* in_sizes, int n_in,
                              void* d_out, int out_size) {
    const float* x         = (const float*)d_in[0];
    const float* ent_emb   = (const float*)d_in[1];
    const float* rel_trans = (const float*)d_in[2];
    const int*   erow      = (const int*)d_in[3];
    const int*   ecol      = (const int*)d_in[4];
    const float* eval      = (const float*)d_in[5];
    float* out             = (float*)d_out;

    const int row_blocks   = (N_ENT + 63) / 64;          // 782
    const int gemm_blocks  = (N_ENT + BM - 1) / BM;      // 391
    const int edge_blocks  = (NEDGE + 255) / 256;        // 6250

    const size_t smem_in   = 2 * 64 * KS_IN * sizeof(float);
    const size_t smem_gemm = (BM * SA_S + BK * SB_S) * sizeof(float);  // 52224
    cudaFuncSetAttribute(k_input_gemm,
                         cudaFuncAttributeMaxDynamicSharedMemorySize, (int)smem_in);
    cudaFuncSetAttribute(k_gemm_relu,
                         cudaFuncAttributeMaxDynamicSharedMemorySize, (int)smem_gemm);

    // input projection
    k_input_gemm<<<row_blocks, 256, smem_in>>>(x, ent_emb, N_ENT);

    // CSR build (once; reused by both layers)
    k_zero_counts<<<(NK / 4 + 255) / 256, 256>>>();
    k_hist<<<edge_blocks, 256>>>(erow);
    k_scan1<<<NCH, 256>>>();
    k_scan2<<<1, 1024>>>();
    k_scan3<<<(NK + 255) / 256, 256>>>();
    k_place<<<edge_blocks, 256>>>(erow, ecol, eval);

    // stacked weights for both layers
    k_wcat<<<(NL * R_REL * D_EMB * D_EMB + 255) / 256, 256>>>(rel_trans);

    for (int l = 0; l < NL; l++) {
        k_gather<<<NK / 8, 256>>>();
        k_gemm_relu<<<gemm_blocks, 256, smem_gemm>>>(l, N_ENT);
    }

    k_normalize<<<(N_ENT + 7) / 8, 256>>>(out);
}

// round 4
// speedup vs baseline: 1.4318x; 1.4318x over previous
#include <cuda_runtime.h>
#include <cstdint>

#define N_ENT 50000
#define R_REL 16
#define D_EMB 64
#define F_IN  128
#define E_EDGE 100000
#define NEDGE (R_REL * E_EDGE)          // 1.6M
#define NL 2

// ---------------- scratch (device globals; allocation-free rule) ------------
__device__ float g_emb[(size_t)N_ENT * D_EMB];                 // 12.8 MB
__device__ float g_Y[(size_t)R_REL * N_ENT * D_EMB];           // 204.8 MB
__device__ int   g_counts[N_ENT];
__device__ int   g_rowstart[N_ENT + 1];
__device__ int   g_cursor[N_ENT];
__device__ int2  g_recs[NEDGE];        // {(r<<16)|col, val bits}

#define SCHUNK 1024
#define NCH ((N_ENT + SCHUNK - 1) / SCHUNK)                    // 49
__device__ int   g_part[NCH];

// ---------------------------------------------------------------------------
// Input GEMM: g_emb[n,d] = sum_k x[n,k] * ent_emb[k,d]   (K=128)  (round-1 proven)
// ---------------------------------------------------------------------------
#define KS_IN 132

__global__ void k_input_gemm(const float* __restrict__ x,
                             const float* __restrict__ ent_emb,
                             int nrows) {
    extern __shared__ float smem[];
    float* sA  = smem;                 // [64][KS_IN]
    float* sBt = smem + 64 * KS_IN;    // [64][KS_IN]

    const int tid  = threadIdx.x;
    const int base = blockIdx.x * 64;

    for (int idx = tid; idx < F_IN * D_EMB; idx += 256) {
        int k = idx / D_EMB, d = idx % D_EMB;
        sBt[d * KS_IN + k] = ent_emb[idx];
    }
    for (int idx4 = tid; idx4 < 64 * (F_IN / 4); idx4 += 256) {
        int row = idx4 / (F_IN / 4), kq = idx4 % (F_IN / 4);
        float4 v = make_float4(0.f, 0.f, 0.f, 0.f);
        if (base + row < nrows)
            v = reinterpret_cast<const float4*>(x + (size_t)(base + row) * F_IN)[kq];
        *reinterpret_cast<float4*>(&sA[row * KS_IN + kq * 4]) = v;
    }
    __syncthreads();

    const int cs = tid & 15;
    const int rs = tid >> 4;
    float acc[4][4];
#pragma unroll
    for (int i = 0; i < 4; i++)
#pragma unroll
        for (int j = 0; j < 4; j++) acc[i][j] = 0.f;

#pragma unroll 8
    for (int kq = 0; kq < F_IN / 4; kq++) {
        float4 a[4], b[4];
#pragma unroll
        for (int i = 0; i < 4; i++)
            a[i] = *reinterpret_cast<const float4*>(&sA[(rs + 16 * i) * KS_IN + kq * 4]);
#pragma unroll
        for (int j = 0; j < 4; j++)
            b[j] = *reinterpret_cast<const float4*>(&sBt[(cs + 16 * j) * KS_IN + kq * 4]);
#pragma unroll
        for (int i = 0; i < 4; i++)
#pragma unroll
            for (int j = 0; j < 4; j++)
                acc[i][j] += a[i].x * b[j].x + a[i].y * b[j].y +
                             a[i].z * b[j].z + a[i].w * b[j].w;
    }

#pragma unroll
    for (int i = 0; i < 4; i++) {
        int row = base + rs + 16 * i;
        if (row < nrows) {
#pragma unroll
            for (int j = 0; j < 4; j++)
                g_emb[(size_t)row * D_EMB + cs + 16 * j] = acc[i][j];
        }
    }
}

// ---------------------------------------------------------------------------
// CSR build over destination row (degree avg 32)
// ---------------------------------------------------------------------------
__global__ void k_zero_counts() {
    int i = blockIdx.x * blockDim.x + threadIdx.x;
    if (i < N_ENT / 4)
        reinterpret_cast<int4*>(g_counts)[i] = make_int4(0, 0, 0, 0);
}

__global__ void k_hist(const int* __restrict__ erow) {
    int i = blockIdx.x * blockDim.x + threadIdx.x;
    if (i >= NEDGE) return;
    atomicAdd(&g_counts[__ldg(erow + i)], 1);
}

__global__ void k_scan1() {
    __shared__ int ss[256];
    int b = blockIdx.x, t = threadIdx.x;
    int base = b * SCHUNK + t * 4;
    int4 c = make_int4(0, 0, 0, 0);
    if (base < N_ENT) c = *reinterpret_cast<const int4*>(&g_counts[base]);
    int s = c.x + c.y + c.z + c.w;
    ss[t] = s;
    __syncthreads();
    for (int off = 1; off < 256; off <<= 1) {
        int v = (t >= off) ? ss[t - off] : 0;
        __syncthreads();
        ss[t] += v;
        __syncthreads();
    }
    int excl = ss[t] - s;
    if (t == 255) g_part[b] = ss[t];
    if (base < N_ENT) {
        int r = excl;
        g_rowstart[base + 0] = r; r += c.x;
        g_rowstart[base + 1] = r; r += c.y;
        g_rowstart[base + 2] = r; r += c.z;
        g_rowstart[base + 3] = r;
    }
}

__global__ void k_scan2() {
    __shared__ int sp[64];
    int t = threadIdx.x;                 // 64 threads
    int v = (t < NCH) ? g_part[t] : 0;
    sp[t] = v;
    __syncthreads();
    for (int off = 1; off < 64; off <<= 1) {
        int x = (t >= off) ? sp[t - off] : 0;
        __syncthreads();
        sp[t] += x;
        __syncthreads();
    }
    if (t < NCH) g_part[t] = sp[t] - v;
    if (t == 63) g_rowstart[N_ENT] = sp[63];
}

__global__ void k_scan3() {
    int i = blockIdx.x * blockDim.x + threadIdx.x;
    if (i < N_ENT) {
        int v = g_rowstart[i] + g_part[i >> 10];
        g_rowstart[i] = v;
        g_cursor[i] = v;
    }
}

__global__ void k_place(const int* __restrict__ erow,
                        const int* __restrict__ ecol,
                        const float* __restrict__ eval) {
    int i = blockIdx.x * blockDim.x + threadIdx.x;
    if (i >= NEDGE) return;
    int r = i / E_EDGE;
    int row = __ldg(erow + i);
    int pos = atomicAdd(&g_cursor[row], 1);
    g_recs[pos] = make_int2((r << 16) | __ldg(ecol + i),
                            __float_as_int(__ldg(eval + i)));
}

// ---------------------------------------------------------------------------
// Transform: Y[r][n][d] = sum_e emb[n][e] * W_r[d][e]   (K=64, N=64)
// 128-row tile, 256 threads; thread tile 4 rows x 8 cols; packed fma.rn.f32x2.
// sBt[e][d] = W[d][e] so d-pairs are contiguous for the f32x2 B operand.
// ---------------------------------------------------------------------------
#define TBM 128
#define TS  68

__global__ void __launch_bounds__(256)
k_transform(const float* __restrict__ rel_trans, int layer, int nrows) {
    extern __shared__ float sm[];
    float* sA  = sm;               // [128][TS]
    float* sBt = sm + TBM * TS;    // [64][TS]

    const int tid  = threadIdx.x;
    const int base = blockIdx.x * TBM;
    const int r    = blockIdx.y;
    const float* W = rel_trans + ((size_t)layer * R_REL + r) * D_EMB * D_EMB; // [d][e]
    float* C       = g_Y + (size_t)r * N_ENT * D_EMB;

    // Bt[e][d] = W[d][e]
    for (int idx = tid; idx < D_EMB * D_EMB; idx += 256) {
        int d = idx >> 6, e = idx & 63;
        sBt[e * TS + d] = W[idx];
    }
    // A tile: 128 rows x 16 float4
#pragma unroll
    for (int i = 0; i < 8; i++) {
        int idx4 = tid + i * 256;
        int row = idx4 >> 4;
        int kq  = idx4 & 15;
        float4 v = make_float4(0.f, 0.f, 0.f, 0.f);
        if (base + row < nrows)
            v = *reinterpret_cast<const float4*>(
                &g_emb[(size_t)(base + row) * D_EMB + kq * 4]);
        *reinterpret_cast<float4*>(&sA[row * TS + kq * 4]) = v;
    }
    __syncthreads();

    const int tr = tid >> 3;    // 0..31: rows tr*4..tr*4+3
    const int tc = tid & 7;     // 0..7 : cols tc*8..tc*8+7

    unsigned long long acc[4][4];
#pragma unroll
    for (int i = 0; i < 4; i++)
#pragma unroll
        for (int j = 0; j < 4; j++) acc[i][j] = 0ull;

#pragma unroll
    for (int k4 = 0; k4 < D_EMB; k4 += 4) {
        float4 av[4];
#pragma unroll
        for (int i = 0; i < 4; i++)
            av[i] = *reinterpret_cast<const float4*>(&sA[(tr * 4 + i) * TS + k4]);
#pragma unroll
        for (int kk = 0; kk < 4; kk++) {
            int k = k4 + kk;
            ulonglong2 b01 = *reinterpret_cast<const ulonglong2*>(&sBt[k * TS + tc * 8]);
            ulonglong2 b23 = *reinterpret_cast<const ulonglong2*>(&sBt[k * TS + tc * 8 + 4]);
            unsigned long long bp0 = b01.x, bp1 = b01.y, bp2 = b23.x, bp3 = b23.y;
#pragma unroll
            for (int i = 0; i < 4; i++) {
                float a = (kk == 0) ? av[i].x : (kk == 1) ? av[i].y
                         : (kk == 2) ? av[i].z : av[i].w;
                unsigned long long a2;
                asm("mov.b64 %0, {%1, %1};" : "=l"(a2) : "f"(a));
                asm("fma.rn.f32x2 %0, %1, %2, %0;" : "+l"(acc[i][0]) : "l"(a2), "l"(bp0));
                asm("fma.rn.f32x2 %0, %1, %2, %0;" : "+l"(acc[i][1]) : "l"(a2), "l"(bp1));
                asm("fma.rn.f32x2 %0, %1, %2, %0;" : "+l"(acc[i][2]) : "l"(a2), "l"(bp2));
                asm("fma.rn.f32x2 %0, %1, %2, %0;" : "+l"(acc[i][3]) : "l"(a2), "l"(bp3));
            }
        }
    }

#pragma unroll
    for (int i = 0; i < 4; i++) {
        int row = base + tr * 4 + i;
        if (row < nrows) {
#pragma unroll
            for (int j = 0; j < 4; j++)
                *reinterpret_cast<float2*>(
                    &C[(size_t)row * D_EMB + tc * 8 + j * 2]) =
                    *reinterpret_cast<float2*>(&acc[i][j]);
        }
    }
}

// ---------------------------------------------------------------------------
// Gather + ReLU: emb[row] = relu( sum_{edges into row} val * Y[r][col] )
// One warp per row (avg degree 32); 2-edge pipelining for MLP; atomic-free.
// ---------------------------------------------------------------------------
__global__ void k_gather_relu() {
    int row  = blockIdx.x * 8 + (threadIdx.x >> 5);
    int lane = threadIdx.x & 31;
    if (row >= N_ENT) return;
    int s = __ldg(&g_rowstart[row]);
    int e = __ldg(&g_rowstart[row + 1]);
    float ax = 0.f, ay = 0.f;
    int j = s;
    for (; j + 2 <= e; j += 2) {
        int2 r0 = __ldg(&g_recs[j]);
        int2 r1 = __ldg(&g_recs[j + 1]);
        size_t o0 = ((size_t)(r0.x >> 16) * N_ENT + (r0.x & 0xFFFF)) * D_EMB;
        size_t o1 = ((size_t)(r1.x >> 16) * N_ENT + (r1.x & 0xFFFF)) * D_EMB;
        float2 p0 = *reinterpret_cast<const float2*>(&g_Y[o0 + lane * 2]);
        float2 p1 = *reinterpret_cast<const float2*>(&g_Y[o1 + lane * 2]);
        float v0 = __int_as_float(r0.y);
        float v1 = __int_as_float(r1.y);
        ax = fmaf(v0, p0.x, ax); ay = fmaf(v0, p0.y, ay);
        ax = fmaf(v1, p1.x, ax); ay = fmaf(v1, p1.y, ay);
    }
    if (j < e) {
        int2 r0 = __ldg(&g_recs[j]);
        size_t o0 = ((size_t)(r0.x >> 16) * N_ENT + (r0.x & 0xFFFF)) * D_EMB;
        float2 p0 = *reinterpret_cast<const float2*>(&g_Y[o0 + lane * 2]);
        float v0 = __int_as_float(r0.y);
        ax = fmaf(v0, p0.x, ax); ay = fmaf(v0, p0.y, ay);
    }
    ax = fmaxf(ax, 0.f);
    ay = fmaxf(ay, 0.f);
    *reinterpret_cast<float2*>(&g_emb[(size_t)row * D_EMB + lane * 2]) =
        make_float2(ax, ay);
}

// ---------------------------------------------------------------------------
// L2 normalize rows
// ---------------------------------------------------------------------------
__global__ void k_normalize(float* __restrict__ out) {
    int row  = blockIdx.x * 8 + (threadIdx.x >> 5);
    int lane = threadIdx.x & 31;
    if (row >= N_ENT) return;
    const float* e = g_emb + (size_t)row * D_EMB;
    float v0 = e[lane], v1 = e[lane + 32];
    float ss = v0 * v0 + v1 * v1;
#pragma unroll
    for (int o = 16; o > 0; o >>= 1) ss += __shfl_xor_sync(0xFFFFFFFFu, ss, o);
    float s = 1.0f / fmaxf(sqrtf(ss), 1e-12f);
    out[(size_t)row * D_EMB + lane]      = v0 * s;
    out[(size_t)row * D_EMB + lane + 32] = v1 * s;
}

// ---------------------------------------------------------------------------
extern "C" void kernel_launch(void* const* d_in, const int* in_sizes, int n_in,
                              void* d_out, int out_size) {
    const float* x         = (const float*)d_in[0];
    const float* ent_emb   = (const float*)d_in[1];
    const float* rel_trans = (const float*)d_in[2];
    const int*   erow      = (const int*)d_in[3];
    const int*   ecol      = (const int*)d_in[4];
    const float* eval      = (const float*)d_in[5];
    float* out             = (float*)d_out;

    const int in_blocks    = (N_ENT + 63) / 64;           // 782
    const int t_blocks     = (N_ENT + TBM - 1) / TBM;     // 391
    const int edge_blocks  = (NEDGE + 255) / 256;         // 6250
    const int row_warps    = (N_ENT + 7) / 8;             // 6250

    const size_t smem_in = 2 * 64 * KS_IN * sizeof(float);
    const size_t smem_t  = (TBM * TS + D_EMB * TS) * sizeof(float);  // 52224
    cudaFuncSetAttribute(k_input_gemm,
                         cudaFuncAttributeMaxDynamicSharedMemorySize, (int)smem_in);
    cudaFuncSetAttribute(k_transform,
                         cudaFuncAttributeMaxDynamicSharedMemorySize, (int)smem_t);

    // launches ordered so #5 (0-based) is k_transform for the ncu capture
    k_input_gemm<<<in_blocks, 256, smem_in>>>(x, ent_emb, N_ENT);      // 0
    k_zero_counts<<<(N_ENT / 4 + 255) / 256, 256>>>();                 // 1
    k_hist<<<edge_blocks, 256>>>(erow);                                // 2
    k_scan1<<<NCH, 256>>>();                                           // 3
    k_scan2<<<1, 64>>>();                                              // 4
    k_transform<<<dim3(t_blocks, R_REL), 256, smem_t>>>(rel_trans, 0, N_ENT); // 5
    k_scan3<<<(N_ENT + 255) / 256, 256>>>();                           // 6
    k_place<<<edge_blocks, 256>>>(erow, ecol, eval);                   // 7
    k_gather_relu<<<row_warps, 256>>>();                               // 8
    k_transform<<<dim3(t_blocks, R_REL), 256, smem_t>>>(rel_trans, 1, N_ENT); // 9
    k_gather_relu<<<row_warps, 256>>>();                               // 10
    k_normalize<<<row_warps, 256>>>(out);                              // 11
}